// round 9
// baseline (speedup 1.0000x reference)
#include <cuda_runtime.h>
#include <math.h>

// Problem constants
#define NGV    256          // graph-views = 128 graphs x 2 views
#define NNODE  256
#define DFEAT  128
#define KBINS  16
#define ROWP4  33           // padded row length in float4 (132 floats) -> conflict-free LDS.128
#define SMEM_BYTES ((NNODE*ROWP4*4 + 256 + 256 + 128) * 4)

// Scratch (static device globals — no runtime allocation)
__device__ float g_D[(size_t)NGV * NNODE * NNODE];   // 64MB pairwise distances
__device__ float g_sig[NGV * KBINS];                 // per-graph-view signatures
__device__ float g_ntx;                              // NT-Xent loss

__device__ __forceinline__ float ex2f(float x) {
    float r; asm("ex2.approx.f32 %0, %1;" : "=f"(r) : "f"(x)); return r;
}

__global__ __launch_bounds__(256, 1)
void k_main(const float* __restrict__ H1, const float* __restrict__ H2,
            const float* __restrict__ Z1, const float* __restrict__ Z2)
{
    extern __shared__ float sh[];
    float4* sh4  = (float4*)sh;                  // [256][33] float4 (padded rows)
    float*  sq   = sh + NNODE * ROWP4 * 4;       // 256 squared norms
    float*  red  = sq + 256;                     // 256 reduction scratch
    float*  hred = red + 256;                    // 8 warps x 16 hist partials

    const int t = threadIdx.x;
    const int b = blockIdx.x;

    if (b < NGV) {
        // ---------------- graph-view block ----------------
        const float* H = ((b & 1) ? H2 : H1) + (size_t)(b >> 1) * (NNODE * DFEAT);
        const float4* Hv = (const float4*)H;

        // Load H (256x128 f32) into padded shared. Coalesced global, conflict-free shared.
        #pragma unroll
        for (int k = 0; k < 32; ++k) {
            int idx = k * 256 + t;                   // 8192 float4 total
            sh4[(idx >> 5) * ROWP4 + (idx & 31)] = Hv[idx];
        }
        __syncthreads();

        // Squared norms (thread t -> row t)
        {
            float s = 0.f;
            #pragma unroll 8
            for (int d4 = 0; d4 < 32; ++d4) {
                float4 v = sh4[t * ROWP4 + d4];
                s += v.x*v.x + v.y*v.y + v.z*v.z + v.w*v.w;
            }
            sq[t] = s;
        }
        __syncthreads();

        // Pass 1: Gram -> D, accumulate sum(D). Thread tile: 4 rows x 64 cols.
        // rows {ig, ig+64, ig+128, ig+192} (stride-64 keeps own-row LDS.128 conflict-free),
        // cols [jh*64, jh*64+64). j-operand loads are warp-uniform broadcasts.
        const int ig = t & 63;
        const int jh = t >> 6;
        float4* gD4 = (float4*)(g_D + (size_t)b * (NNODE * NNODE));

        float sqi[4];
        #pragma unroll
        for (int r = 0; r < 4; ++r) sqi[r] = sq[ig + 64 * r];

        float sumD = 0.f;
        for (int jt = 0; jt < 4; ++jt) {
            const int j0 = jh * 64 + jt * 16;
            float acc[4][16];
            #pragma unroll
            for (int r = 0; r < 4; ++r)
                #pragma unroll
                for (int u = 0; u < 16; ++u) acc[r][u] = 0.f;

            for (int d4 = 0; d4 < 32; ++d4) {
                float4 a0 = sh4[(ig      ) * ROWP4 + d4];
                float4 a1 = sh4[(ig +  64) * ROWP4 + d4];
                float4 a2 = sh4[(ig + 128) * ROWP4 + d4];
                float4 a3 = sh4[(ig + 192) * ROWP4 + d4];
                #pragma unroll
                for (int u = 0; u < 16; ++u) {
                    float4 bb = sh4[(j0 + u) * ROWP4 + d4];
                    acc[0][u] += a0.x*bb.x + a0.y*bb.y + a0.z*bb.z + a0.w*bb.w;
                    acc[1][u] += a1.x*bb.x + a1.y*bb.y + a1.z*bb.z + a1.w*bb.w;
                    acc[2][u] += a2.x*bb.x + a2.y*bb.y + a2.z*bb.z + a2.w*bb.w;
                    acc[3][u] += a3.x*bb.x + a3.y*bb.y + a3.z*bb.z + a3.w*bb.w;
                }
            }
            // Epilogue: D = sqrt(max(d2,0)+1e-12), store, accumulate sum
            #pragma unroll
            for (int r = 0; r < 4; ++r) {
                const int row = ig + 64 * r;
                #pragma unroll
                for (int u4 = 0; u4 < 4; ++u4) {
                    float4 dv;
                    float* dp = (float*)&dv;
                    #pragma unroll
                    for (int c = 0; c < 4; ++c) {
                        const int u = u4 * 4 + c;
                        float d2 = sqi[r] + sq[j0 + u] - 2.f * acc[r][u];
                        float x  = fmaxf(d2, 0.f) + 1e-12f;
                        float dd = x * rsqrtf(x);          // sqrt via MUFU.RSQ
                        dp[c] = dd;
                        sumD += dd;
                    }
                    gD4[row * 64 + (j0 >> 2) + u4] = dv;
                }
            }
        }

        // Block reduce sum(D) (deterministic tree)
        red[t] = sumD;
        __syncthreads();
        for (int s = 128; s > 0; s >>= 1) {
            if (t < s) red[t] += red[t + s];
            __syncthreads();
        }
        const float invMean = 1.f / (red[0] * (1.f / 65536.f) + 1e-8f);
        __syncthreads();   // protect red[] before reuse below

        // Pass 2: soft histogram. Linear coalesced re-read of D (order-independent sum).
        float hist[KBINS];
        #pragma unroll
        for (int k = 0; k < KBINS; ++k) hist[k] = 0.f;
        const float C2 = -(0.5f / (0.1875f * 0.1875f)) * 1.4426950408889634f; // base-2 exponent coeff

        for (int k = 0; k < 64; ++k) {
            float4 dv = gD4[k * 256 + t];
            float dd[4] = {dv.x, dv.y, dv.z, dv.w};
            #pragma unroll
            for (int c = 0; c < 4; ++c) {
                float dn = dd[c] * invMean;
                #pragma unroll
                for (int kk = 0; kk < KBINS; ++kk) {
                    float tt = dn - 0.2f * (float)kk;
                    hist[kk] += ex2f(C2 * tt * tt);
                }
            }
        }

        // Hist reduction: warp shuffle -> shared -> 16 threads
        {
            const int wid = t >> 5, lane = t & 31;
            #pragma unroll
            for (int kk = 0; kk < KBINS; ++kk) {
                float v = hist[kk];
                #pragma unroll
                for (int off = 16; off; off >>= 1) v += __shfl_down_sync(0xffffffffu, v, off);
                if (lane == 0) hred[wid * KBINS + kk] = v;
            }
            __syncthreads();
            if (t < KBINS) {
                float v = 0.f;
                #pragma unroll
                for (int w = 0; w < 8; ++w) v += hred[w * KBINS + t];
                red[t] = v;
            }
            __syncthreads();
            if (t < KBINS) {
                float tot = 0.f;
                #pragma unroll
                for (int kk = 0; kk < KBINS; ++kk) tot += red[kk];
                g_sig[b * KBINS + t] = red[t] / (tot + 1e-8f);
            }
        }
    } else {
        // ---------------- NT-Xent block (b == 256) ----------------
        // Load z = [z1; z2] (256 x 128) into padded shared
        #pragma unroll
        for (int k = 0; k < 32; ++k) {
            int idx = k * 256 + t;
            int row = idx >> 5, d4 = idx & 31;
            const float4* Z = (row < 128) ? ((const float4*)Z1 + row * 32)
                                          : ((const float4*)Z2 + (row - 128) * 32);
            sh4[row * ROWP4 + d4] = Z[d4];
        }
        __syncthreads();

        // Row-normalize in place: z / (||z|| + eps)
        {
            float ssum = 0.f;
            #pragma unroll 8
            for (int d4 = 0; d4 < 32; ++d4) {
                float4 v = sh4[t * ROWP4 + d4];
                ssum += v.x*v.x + v.y*v.y + v.z*v.z + v.w*v.w;
            }
            float nrm = ssum * rsqrtf(fmaxf(ssum, 1e-30f));
            float rn = 1.f / (nrm + 1e-8f);
            #pragma unroll 8
            for (int d4 = 0; d4 < 32; ++d4) {
                float4 v = sh4[t * ROWP4 + d4];
                v.x *= rn; v.y *= rn; v.z *= rn; v.w *= rn;
                sh4[t * ROWP4 + d4] = v;
            }
        }
        __syncthreads();

        // Thread t owns sim row t; streaming (online) logsumexp over 16-col tiles.
        const int lab = (t + 128) & 255;
        float m = -INFINITY, s = 0.f, num = 0.f;
        const float L2E = 1.4426950408889634f;

        for (int jt = 0; jt < 16; ++jt) {
            const int j0 = jt * 16;
            float acc[16];
            #pragma unroll
            for (int u = 0; u < 16; ++u) acc[u] = 0.f;
            for (int d4 = 0; d4 < 32; ++d4) {
                float4 a = sh4[t * ROWP4 + d4];
                #pragma unroll
                for (int u = 0; u < 16; ++u) {
                    float4 bb = sh4[(j0 + u) * ROWP4 + d4];
                    acc[u] += a.x*bb.x + a.y*bb.y + a.z*bb.z + a.w*bb.w;
                }
            }
            #pragma unroll
            for (int u = 0; u < 16; ++u) {
                const int j = j0 + u;
                float v = 2.f * acc[u];          // / TEMP (0.5)
                if (j == t)   v = -1e9f;         // diag mask
                if (j == lab) num = v;           // positive pair logit
                float nm = fmaxf(m, v);
                s = s * ex2f((m - nm) * L2E) + ex2f((v - nm) * L2E);
                m = nm;
            }
        }
        float li = (m + logf(s)) - num;          // logsumexp - sim[i, label]
        red[t] = li;
        __syncthreads();
        for (int st = 128; st > 0; st >>= 1) {
            if (t < st) red[t] += red[t + st];
            __syncthreads();
        }
        if (t == 0) g_ntx = red[0] * (1.f / 256.f);
    }
}

__global__ void k_final(float* __restrict__ out, int out_size)
{
    __shared__ float red[128];
    const int t = threadIdx.x;   // 128 threads, t = graph index
    float v = 0.f;
    #pragma unroll
    for (int k = 0; k < KBINS; ++k) {
        float d = g_sig[(2 * t) * KBINS + k] - g_sig[(2 * t + 1) * KBINS + k];
        v += d * d;
    }
    v *= (1.f / (float)KBINS);   // mean over K
    red[t] = v;
    __syncthreads();
    for (int s = 64; s > 0; s >>= 1) {
        if (t < s) red[t] += red[t + s];
        __syncthreads();
    }
    float result = 0.1f * (red[0] * (1.f / 128.f) + g_ntx);   // LAMBDA = 0.1
    for (int i = t; i < out_size; i += 128) out[i] = result;
}

extern "C" void kernel_launch(void* const* d_in, const int* in_sizes, int n_in,
                              void* d_out, int out_size)
{
    // metadata order: H1, batch1, H2, batch2, z1, z2 (batch arrays unused: equal-size graphs)
    const float* H1 = (const float*)d_in[0];
    const float* H2 = (const float*)d_in[2];
    const float* Z1 = (const float*)d_in[4];
    const float* Z2 = (const float*)d_in[5];

    cudaFuncSetAttribute(k_main, cudaFuncAttributeMaxDynamicSharedMemorySize, SMEM_BYTES);

    k_main<<<NGV + 1, 256, SMEM_BYTES>>>(H1, H2, Z1, Z2);
    k_final<<<1, 128>>>((float*)d_out, out_size);
}

// round 12
// speedup vs baseline: 2.2952x; 2.2952x over previous
#include <cuda_runtime.h>
#include <cuda_bf16.h>
#include <math.h>

#define NGV    256
#define KBINS  16
#define ROWU4  17                      // padded row in uint4 (16 data + 1) -> conflict-free LDS.128
#define SM_H_BYTES (256 * ROWU4 * 16)  // 69632
#define SMEM_BYTES (SM_H_BYTES + (256 + 256 + 128) * 4)

__device__ __align__(16) float g_D[(size_t)NGV * 40960];  // 10 upper tiles x 4096 per block (~42MB)
__device__ float g_sig[NGV * KBINS];
__device__ float g_ntx2[2];

// Upper-triangular 64x64 tile list: 0-3 diagonal, 4-9 off-diagonal
__constant__ unsigned char c_tp[10] = {0,1,2,3, 0,0,0,1,1,2};
__constant__ unsigned char c_tq[10] = {0,1,2,3, 1,2,3,2,3,3};

__device__ __forceinline__ float ex2f(float x) {
    float r; asm("ex2.approx.f32 %0, %1;" : "=f"(r) : "f"(x)); return r;
}
__device__ __forceinline__ __nv_bfloat162 asbf2(unsigned int u) {
    __nv_bfloat162 h; *reinterpret_cast<unsigned int*>(&h) = u; return h;
}
__device__ __forceinline__ unsigned int asu32(__nv_bfloat162 h) {
    return *reinterpret_cast<unsigned int*>(&h);
}
__device__ __forceinline__ float pairsum(__nv_bfloat162 h) {
    float2 f = __bfloat1622float2(h); return f.x + f.y;
}
__device__ __forceinline__ float sq2f(unsigned int u) {
    float2 f = __bfloat1622float2(asbf2(u)); return f.x*f.x + f.y*f.y;
}
__device__ __forceinline__ uint4 pack8(float4 v0, float4 v1) {
    uint4 o;
    o.x = asu32(__floats2bfloat162_rn(v0.x, v0.y));
    o.y = asu32(__floats2bfloat162_rn(v0.z, v0.w));
    o.z = asu32(__floats2bfloat162_rn(v1.x, v1.y));
    o.w = asu32(__floats2bfloat162_rn(v1.z, v1.w));
    return o;
}

__global__ __launch_bounds__(256, 2)
void k_main(const float* __restrict__ H1, const float* __restrict__ H2,
            const float* __restrict__ Z1, const float* __restrict__ Z2)
{
    extern __shared__ char smraw[];
    uint4* shH  = (uint4*)smraw;                    // 256 rows x 17 uint4 (bf16x2 x4)
    float* sq   = (float*)(smraw + SM_H_BYTES);     // 256
    float* red  = sq + 256;                         // 256
    float* hred = red + 256;                        // 128

    const int t = threadIdx.x;
    const int b = blockIdx.x;

    if (b < NGV) {
        // ================= graph-view block =================
        const float4* Hv = (const float4*)(((b & 1) ? H2 : H1) + (size_t)(b >> 1) * (256 * 128));
        #pragma unroll
        for (int k = 0; k < 16; ++k) {
            int idx = k * 256 + t, row = idx >> 4, u4 = idx & 15;
            shH[row * ROWU4 + u4] = pack8(Hv[row * 32 + u4 * 2], Hv[row * 32 + u4 * 2 + 1]);
        }
        __syncthreads();

        {   // squared norms (fp32, from quantized values)
            float s = 0.f;
            #pragma unroll
            for (int u4 = 0; u4 < 16; ++u4) {
                uint4 v = shH[t * ROWU4 + u4];
                s += sq2f(v.x) + sq2f(v.y) + sq2f(v.z) + sq2f(v.w);
            }
            sq[t] = s;
        }
        __syncthreads();

        // ---- Pass 1: symmetric Gram over 20 half-tile jobs (64x32 each) ----
        const int g  = t >> 6;        // group 0..3 (each does 5 jobs)
        const int a  = t & 63;
        const int s_ = a & 31;        // row index within block half
        const int ch = a >> 5;        // 16-col chunk (warp-uniform)
        float sumd = 0.f, sumo = 0.f;
        float* gDb = g_D + (size_t)b * 40960;

        for (int k = 0; k < 5; ++k) {
            const int job = 4 * k + g;              // 0..19
            const int tile = job >> 1, colh = job & 1;
            const int p = c_tp[tile], q = c_tq[tile];
            const int r0 = 64 * p + s_;             // rows r0, r0+32 (conflict-free LDS)
            const int r1 = r0 + 32;
            const int cbase = 64 * q + 32 * colh + 16 * ch;
            const uint4* A0 = shH + r0 * ROWU4;
            const uint4* A1 = shH + r1 * ROWU4;
            const uint4* B  = shH + cbase * ROWU4;

            __nv_bfloat162 acc[2][16];
            #pragma unroll
            for (int r = 0; r < 2; ++r)
                #pragma unroll
                for (int u = 0; u < 16; ++u) acc[r][u] = __floats2bfloat162_rn(0.f, 0.f);

            #pragma unroll 2
            for (int d = 0; d < 16; ++d) {
                uint4 av0 = A0[d], av1 = A1[d];
                __nv_bfloat162 a00 = asbf2(av0.x), a01 = asbf2(av0.y),
                               a02 = asbf2(av0.z), a03 = asbf2(av0.w);
                __nv_bfloat162 a10 = asbf2(av1.x), a11 = asbf2(av1.y),
                               a12 = asbf2(av1.z), a13 = asbf2(av1.w);
                #pragma unroll
                for (int u = 0; u < 16; ++u) {
                    uint4 bv = B[u * ROWU4 + d];    // warp-uniform broadcast
                    acc[0][u] = __hfma2(a00, asbf2(bv.x), acc[0][u]);
                    acc[0][u] = __hfma2(a01, asbf2(bv.y), acc[0][u]);
                    acc[0][u] = __hfma2(a02, asbf2(bv.z), acc[0][u]);
                    acc[0][u] = __hfma2(a03, asbf2(bv.w), acc[0][u]);
                    acc[1][u] = __hfma2(a10, asbf2(bv.x), acc[1][u]);
                    acc[1][u] = __hfma2(a11, asbf2(bv.y), acc[1][u]);
                    acc[1][u] = __hfma2(a12, asbf2(bv.z), acc[1][u]);
                    acc[1][u] = __hfma2(a13, asbf2(bv.w), acc[1][u]);
                }
            }

            const bool isdiag = (tile < 4);
            float4* outp = (float4*)gDb + job * 512;
            float js = 0.f;
            #pragma unroll
            for (int r = 0; r < 2; ++r) {
                const int gi = r0 + 32 * r;
                const float sqi = sq[gi];
                #pragma unroll
                for (int u4 = 0; u4 < 4; ++u4) {
                    float4 dv; float* dp = (float*)&dv;
                    #pragma unroll
                    for (int c = 0; c < 4; ++c) {
                        const int u = u4 * 4 + c;
                        float d2 = sqi + sq[cbase + u] - 2.f * pairsum(acc[r][u]);
                        float x  = fmaxf(d2, 0.f) + 1e-12f;
                        float dd = x * rsqrtf(x);
                        if (isdiag && (gi == cbase + u)) dd = 1e-6f;
                        dp[c] = dd; js += dd;
                    }
                    outp[(ch * 4 + u4) * 64 + s_ + 32 * r] = dv;  // coalesced
                }
            }
            if (isdiag) sumd += js; else sumo += js;
        }

        red[t] = 2.f * sumo + sumd;   // ordered-pair sum via symmetry
        __syncthreads();
        for (int st = 128; st > 0; st >>= 1) {
            if (t < st) red[t] += red[t + st];
            __syncthreads();
        }
        const float invMean = 1.f / (red[0] * (1.f / 65536.f) + 1e-8f);
        __syncthreads();

        // ---- Pass 2: soft histogram (diag tiles weight 1, off-diag weight 2) ----
        float hd[KBINS], ho[KBINS];
        #pragma unroll
        for (int kk = 0; kk < KBINS; ++kk) { hd[kk] = 0.f; ho[kk] = 0.f; }
        const float S = 4.529896f;     // sqrt(0.5/sigma^2 * log2(e)), sigma=0.1875
        const float4* gp = (const float4*)gDb;

        #pragma unroll 2
        for (int i = 0; i < 16; ++i) {             // diag region: jobs 0-7
            float4 dv = gp[i * 256 + t];
            float dd[4] = {dv.x, dv.y, dv.z, dv.w};
            #pragma unroll
            for (int c = 0; c < 4; ++c) {
                float dns = dd[c] * invMean * S;
                #pragma unroll
                for (int kk = 0; kk < KBINS; ++kk) {
                    float y = dns - (0.2f * S) * (float)kk;
                    hd[kk] += ex2f(-y * y);
                }
            }
        }
        #pragma unroll 2
        for (int i = 16; i < 40; ++i) {            // off-diag region: jobs 8-19
            float4 dv = gp[i * 256 + t];
            float dd[4] = {dv.x, dv.y, dv.z, dv.w};
            #pragma unroll
            for (int c = 0; c < 4; ++c) {
                float dns = dd[c] * invMean * S;
                #pragma unroll
                for (int kk = 0; kk < KBINS; ++kk) {
                    float y = dns - (0.2f * S) * (float)kk;
                    ho[kk] += ex2f(-y * y);
                }
            }
        }

        {   // hist reduction
            const int wid = t >> 5, lane = t & 31;
            #pragma unroll
            for (int kk = 0; kk < KBINS; ++kk) {
                float v = 2.f * ho[kk] + hd[kk];
                #pragma unroll
                for (int off = 16; off; off >>= 1) v += __shfl_down_sync(0xffffffffu, v, off);
                if (lane == 0) hred[wid * KBINS + kk] = v;
            }
            __syncthreads();
            if (t < KBINS) {
                float v = 0.f;
                #pragma unroll
                for (int w = 0; w < 8; ++w) v += hred[w * KBINS + t];
                red[t] = v;
            }
            __syncthreads();
            if (t < KBINS) {
                float tot = 0.f;
                #pragma unroll
                for (int kk = 0; kk < KBINS; ++kk) tot += red[kk];
                g_sig[b * KBINS + t] = red[t] / (tot + 1e-8f);
            }
        }
    } else {
        // ================= NT-Xent blocks (b = 256, 257): 128 rows each =================
        #pragma unroll
        for (int k = 0; k < 16; ++k) {
            int idx = k * 256 + t, row = idx >> 4, u4 = idx & 15;
            const float4* Zr = (row < 128) ? ((const float4*)Z1 + row * 32)
                                           : ((const float4*)Z2 + (row - 128) * 32);
            shH[row * ROWU4 + u4] = pack8(Zr[u4 * 2], Zr[u4 * 2 + 1]);
        }
        __syncthreads();

        {   // row-normalize (fp32 norm of quantized values, restore bf16)
            float ss = 0.f;
            #pragma unroll
            for (int u4 = 0; u4 < 16; ++u4) {
                uint4 v = shH[t * ROWU4 + u4];
                ss += sq2f(v.x) + sq2f(v.y) + sq2f(v.z) + sq2f(v.w);
            }
            float rn = 1.f / (sqrtf(ss) + 1e-8f);
            #pragma unroll
            for (int u4 = 0; u4 < 16; ++u4) {
                uint4 v = shH[t * ROWU4 + u4];
                unsigned int* pv = (unsigned int*)&v;
                #pragma unroll
                for (int c = 0; c < 4; ++c) {
                    float2 f = __bfloat1622float2(asbf2(pv[c]));
                    pv[c] = asu32(__floats2bfloat162_rn(f.x * rn, f.y * rn));
                }
                shH[t * ROWU4 + u4] = v;
            }
        }
        __syncthreads();

        // thread: row gi, column half chs. Split-K bf16 Gram (fp32 chunk sums).
        const int rl  = t & 127;
        const int chs = t >> 7;
        const int gi  = (b - NGV) * 128 + rl;
        const int lab = (gi + 128) & 255;
        const float L2E = 1.4426950408889634f;
        float m = -INFINITY, ssum = 0.f, num = 0.f;
        const uint4* Arow = shH + gi * ROWU4;

        for (int jt = 0; jt < 8; ++jt) {
            const int j0 = chs * 128 + jt * 16;
            float accf[16];
            #pragma unroll
            for (int u = 0; u < 16; ++u) accf[u] = 0.f;
            for (int cku = 0; cku < 4; ++cku) {            // 4 chunks x 32 features
                __nv_bfloat162 acc2[16];
                #pragma unroll
                for (int u = 0; u < 16; ++u) acc2[u] = __floats2bfloat162_rn(0.f, 0.f);
                #pragma unroll
                for (int dd = 0; dd < 4; ++dd) {
                    const int d = cku * 4 + dd;
                    uint4 av = Arow[d];
                    __nv_bfloat162 a0 = asbf2(av.x), a1 = asbf2(av.y),
                                   a2 = asbf2(av.z), a3 = asbf2(av.w);
                    #pragma unroll
                    for (int u = 0; u < 16; ++u) {
                        uint4 bv = shH[(j0 + u) * ROWU4 + d];
                        acc2[u] = __hfma2(a0, asbf2(bv.x), acc2[u]);
                        acc2[u] = __hfma2(a1, asbf2(bv.y), acc2[u]);
                        acc2[u] = __hfma2(a2, asbf2(bv.z), acc2[u]);
                        acc2[u] = __hfma2(a3, asbf2(bv.w), acc2[u]);
                    }
                }
                #pragma unroll
                for (int u = 0; u < 16; ++u) accf[u] += pairsum(acc2[u]);
            }
            #pragma unroll
            for (int u = 0; u < 16; ++u) {
                const int j = j0 + u;
                float v = 2.f * accf[u];        // / TEMP
                if (j == gi)  v = -1e9f;
                if (j == lab) num = v;
                float nm = fmaxf(m, v);
                ssum = ssum * ex2f((m - nm) * L2E) + ex2f((v - nm) * L2E);
                m = nm;
            }
        }

        // merge the two column halves, then reduce rows
        if (chs == 1) { red[rl] = m; red[128 + rl] = ssum; hred[rl] = num; }
        __syncthreads();
        if (chs == 0) {
            float m1 = red[rl], s1 = red[128 + rl];
            float M  = fmaxf(m, m1);
            float SS = ssum * ex2f((m - M) * L2E) + s1 * ex2f((m1 - M) * L2E);
            float nn = ((lab >> 7) == 0) ? num : hred[rl];
            sq[rl] = (M + logf(SS)) - nn;
        }
        __syncthreads();
        for (int st = 64; st > 0; st >>= 1) {
            if (t < st) sq[t] += sq[t + st];
            __syncthreads();
        }
        if (t == 0) g_ntx2[b - NGV] = sq[0];    // unnormalized partial
    }
}

__global__ void k_final(float* __restrict__ out, int out_size)
{
    __shared__ float red[128];
    const int t = threadIdx.x;
    float v = 0.f;
    #pragma unroll
    for (int k = 0; k < KBINS; ++k) {
        float d = g_sig[(2 * t) * KBINS + k] - g_sig[(2 * t + 1) * KBINS + k];
        v += d * d;
    }
    red[t] = v * (1.f / (float)KBINS);
    __syncthreads();
    for (int s = 64; s > 0; s >>= 1) {
        if (t < s) red[t] += red[t + s];
        __syncthreads();
    }
    float ntx = (g_ntx2[0] + g_ntx2[1]) * (1.f / 256.f);
    float result = 0.1f * (red[0] * (1.f / 128.f) + ntx);
    for (int i = t; i < out_size; i += 128) out[i] = result;
}

extern "C" void kernel_launch(void* const* d_in, const int* in_sizes, int n_in,
                              void* d_out, int out_size)
{
    const float* H1 = (const float*)d_in[0];
    const float* H2 = (const float*)d_in[2];
    const float* Z1 = (const float*)d_in[4];
    const float* Z2 = (const float*)d_in[5];

    cudaFuncSetAttribute(k_main, cudaFuncAttributeMaxDynamicSharedMemorySize, SMEM_BYTES);

    k_main<<<NGV + 2, 256, SMEM_BYTES>>>(H1, H2, Z1, Z2);
    k_final<<<1, 128>>>((float*)d_out, out_size);
}

// round 14
// speedup vs baseline: 4.1834x; 1.8227x over previous
#include <cuda_runtime.h>
#include <cuda_bf16.h>
#include <math.h>
#include <stdint.h>

#define NGV    256
#define KBINS  16
#define ROWU4  17                      // padded row: 17 uint4 = 272B (136 bf16 slots, 128 used)
#define ROWW   68                      // row stride in 32-bit words
#define SCR_OFF 69632                  // 256 * 272
#define SMEM_BYTES (SCR_OFF + 2560)

// g_D per block: 10 upper 64x64 tiles: 4 diag (16384 f32) + 6 off (24576 f32)
__device__ __align__(16) float g_D[(size_t)NGV * 40960];
__device__ float g_sig[NGV * KBINS];
__device__ float g_ntx2[2];

// Upper-triangular 64x64 tile list: 0-3 diagonal, 4-9 off-diagonal
__constant__ unsigned char c_tp[10] = {0,1,2,3, 0,0,0,1,1,2};
__constant__ unsigned char c_tq[10] = {0,1,2,3, 1,2,3,2,3,3};

// ---------------- helpers ----------------
__device__ __forceinline__ float ex2f(float x) {
    float r; asm("ex2.approx.f32 %0, %1;" : "=f"(r) : "f"(x)); return r;
}
__device__ __forceinline__ __nv_bfloat162 asbf2(unsigned int u) {
    __nv_bfloat162 h; *reinterpret_cast<unsigned int*>(&h) = u; return h;
}
__device__ __forceinline__ unsigned int asu32(__nv_bfloat162 h) {
    return *reinterpret_cast<unsigned int*>(&h);
}
__device__ __forceinline__ float pairsum(__nv_bfloat162 h) {
    float2 f = __bfloat1622float2(h); return f.x + f.y;
}
__device__ __forceinline__ float sq2f(unsigned int u) {
    float2 f = __bfloat1622float2(asbf2(u)); return f.x*f.x + f.y*f.y;
}
__device__ __forceinline__ uint4 pack8(float4 v0, float4 v1) {
    uint4 o;
    o.x = asu32(__floats2bfloat162_rn(v0.x, v0.y));
    o.y = asu32(__floats2bfloat162_rn(v0.z, v0.w));
    o.z = asu32(__floats2bfloat162_rn(v1.x, v1.y));
    o.w = asu32(__floats2bfloat162_rn(v1.z, v1.w));
    return o;
}

// Warp-level bf16 HMMA: D(16x8,f32) += A(16x16,row) * B(16x8,col)
__device__ __forceinline__ void mma16816(float* d,
                                         uint32_t a0, uint32_t a1, uint32_t a2, uint32_t a3,
                                         uint32_t b0, uint32_t b1) {
    asm volatile(
        "mma.sync.aligned.m16n8k16.row.col.f32.bf16.bf16.f32 "
        "{%0,%1,%2,%3}, {%4,%5,%6,%7}, {%8,%9}, {%0,%1,%2,%3};"
        : "+f"(d[0]), "+f"(d[1]), "+f"(d[2]), "+f"(d[3])
        : "r"(a0), "r"(a1), "r"(a2), "r"(a3), "r"(b0), "r"(b1));
}

__global__ __launch_bounds__(256, 2)
void k_main(const float* __restrict__ H1, const float* __restrict__ H2,
            const float* __restrict__ Z1, const float* __restrict__ Z2)
{
    extern __shared__ char sm[];
    float* sq   = (float*)(sm + SCR_OFF);           // 256
    float* red  = sq + 256;                         // 256
    float* hred = red + 256;                        // 128

    const int t = threadIdx.x;
    const int b = blockIdx.x;
    const int w = t >> 5, lane = t & 31;

    if (b < NGV) {
        // ================= graph-view block =================
        const float4* Hv = (const float4*)(((b & 1) ? H2 : H1) + (size_t)(b >> 1) * (256 * 128));
        uint4* shR = (uint4*)sm;                    // rows of 17 uint4 (16 data + 1 pad)

        // quantize H -> bf16 rows (padded, conflict-free for frag loads)
        #pragma unroll
        for (int k = 0; k < 16; ++k) {
            int idx = k * 256 + t, row = idx >> 4, u4 = idx & 15;
            shR[row * ROWU4 + u4] = pack8(Hv[row * 32 + u4 * 2], Hv[row * 32 + u4 * 2 + 1]);
        }
        __syncthreads();

        {   // squared norms from quantized values (thread t -> row t)
            float s = 0.f;
            #pragma unroll
            for (int u4 = 0; u4 < 16; ++u4) {
                uint4 v = shR[t * ROWU4 + u4];
                s += sq2f(v.x) + sq2f(v.y) + sq2f(v.z) + sq2f(v.w);
            }
            sq[t] = s;
        }
        __syncthreads();

        // ---- Pass 1: Gram via HMMA over 40 jobs (16 rows x 64 cols), 5 per warp ----
        const uint32_t* Hw = (const uint32_t*)sm;
        const int gr = lane >> 2;       // 0..7  (row within 8-row group)
        const int tq = lane & 3;        // 0..3  (thread-in-group)
        float sumd = 0.f, sumo = 0.f;
        float* gDb = g_D + (size_t)b * 40960;

        for (int jj = 0; jj < 5; ++jj) {
            const int j = w + 8 * jj;                // 0..39
            const int tile = j >> 2, rq = j & 3;
            const int p = c_tp[tile], q = c_tq[tile];
            const int r0 = 64 * p + 16 * rq;
            const int rowA  = (r0 + gr) * ROWW;
            const int rowA8 = rowA + 8 * ROWW;
            const int cb64  = 64 * q;

            float acc[8][4];
            #pragma unroll
            for (int nt = 0; nt < 8; ++nt)
                #pragma unroll
                for (int c = 0; c < 4; ++c) acc[nt][c] = 0.f;

            #pragma unroll
            for (int ks = 0; ks < 8; ++ks) {
                const int o = ks * 8 + tq;
                uint32_t a0 = Hw[rowA  + o];
                uint32_t a1 = Hw[rowA8 + o];
                uint32_t a2 = Hw[rowA  + o + 4];
                uint32_t a3 = Hw[rowA8 + o + 4];
                #pragma unroll
                for (int nt = 0; nt < 8; ++nt) {
                    const int rowB = (cb64 + nt * 8 + gr) * ROWW;
                    uint32_t b0 = Hw[rowB + o];
                    uint32_t b1 = Hw[rowB + o + 4];
                    mma16816(acc[nt], a0, a1, a2, a3, b0, b1);
                }
            }

            // Epilogue: d2 -> D -> store tile-local row-major; accumulate sums
            const bool isdiag = (tile < 4);
            const int lr0 = 16 * rq + gr;            // tile-local rows lr0, lr0+8
            const float sqi0 = sq[r0 + gr];
            const float sqi8 = sq[r0 + gr + 8];
            float* ob = gDb + (isdiag ? (size_t)tile * 4096
                                      : (size_t)(16384 + (tile - 4) * 4096));
            float ls = 0.f;
            #pragma unroll
            for (int nt = 0; nt < 8; ++nt) {
                const int cb = nt * 8 + 2 * tq;      // tile-local col (even)
                const float sc0 = sq[cb64 + cb];
                const float sc1 = sq[cb64 + cb + 1];

                float d2a = sqi0 + sc0 - 2.f * acc[nt][0];
                float d2b = sqi0 + sc1 - 2.f * acc[nt][1];
                float d2c = sqi8 + sc0 - 2.f * acc[nt][2];
                float d2d = sqi8 + sc1 - 2.f * acc[nt][3];
                float xa = fmaxf(d2a, 0.f) + 1e-12f;
                float xb = fmaxf(d2b, 0.f) + 1e-12f;
                float xc = fmaxf(d2c, 0.f) + 1e-12f;
                float xd = fmaxf(d2d, 0.f) + 1e-12f;
                float da = xa * rsqrtf(xa);
                float db = xb * rsqrtf(xb);
                float dc = xc * rsqrtf(xc);
                float dd = xd * rsqrtf(xd);
                if (isdiag) {                         // diagonal -> 1e-6 (ref: sqrt(eps)-noise, bin 0)
                    if (lr0 == cb)         da = 1e-6f;
                    if (lr0 == cb + 1)     db = 1e-6f;
                    if (lr0 + 8 == cb)     dc = 1e-6f;
                    if (lr0 + 8 == cb + 1) dd = 1e-6f;
                }
                ls += (da + db) + (dc + dd);
                *(float2*)(ob + (size_t)lr0 * 64 + cb)       = make_float2(da, db);
                *(float2*)(ob + (size_t)(lr0 + 8) * 64 + cb) = make_float2(dc, dd);
            }
            if (isdiag) sumd += ls; else sumo += ls;
        }

        // ---- mean over all 65536 ordered pairs (symmetry weights) ----
        red[t] = 2.f * sumo + sumd;
        __syncthreads();
        for (int st = 128; st > 0; st >>= 1) {
            if (t < st) red[t] += red[t + st];
            __syncthreads();
        }
        const float invMean = 1.f / (red[0] * (1.f / 65536.f) + 1e-8f);
        __syncthreads();

        // ---- Pass 2: factorized soft histogram (3 MUFU / value) ----
        // w_k = 2^(-AL*(x-c_k)^2 * ...): w8 at center c=1.6; neighbors via exact
        // telescoping ratios  w_{k+1} = w_k * Bp * upc,  w_{k-1} = w_k * Bm * dnc.
        const float AL = 20.5183294f;   // alpha*log2e, alpha = 0.5/sigma^2 = 128/9
        const float BC = 8.2073318f;    // 2*alpha*0.2*log2e
        const float SC = 0.82073318f;   // alpha*0.04*log2e
        float upc[7], dnc[8];
        #pragma unroll
        for (int jq = 0; jq < 7; ++jq) upc[jq] = ex2f(-SC * (float)(17 + 2 * jq));
        #pragma unroll
        for (int iq = 0; iq < 8; ++iq) dnc[iq] = ex2f( SC * (float)(15 - 2 * iq));

        float acc[KBINS];
        #pragma unroll
        for (int kk = 0; kk < KBINS; ++kk) acc[kk] = 0.f;

        auto value = [&](float dd) {
            float x  = fminf(dd * invMean, 8.f);     // beyond: all weights 0 (matches fp32 underflow)
            float y  = x - 1.6f;
            float w8 = ex2f(-AL * y * y);
            float u  = BC * x;
            float Bp = ex2f(u);
            float Bm = ex2f(-u);
            acc[8] += w8;
            float wk = w8;
            #pragma unroll
            for (int k = 9; k <= 15; ++k) { wk *= Bp; wk *= upc[k - 9]; acc[k] += wk; }
            wk = w8;
            #pragma unroll
            for (int k = 7; k >= 0; --k) { wk *= Bm; wk *= dnc[7 - k]; acc[k] += wk; }
        };

        const float4* gp = (const float4*)gDb;
        #pragma unroll 2
        for (int i = 16; i < 40; ++i) {              // off-diag region first
            float4 dv = gp[i * 256 + t];
            value(dv.x); value(dv.y); value(dv.z); value(dv.w);
        }
        #pragma unroll
        for (int kk = 0; kk < KBINS; ++kk) acc[kk] *= 2.f;   // symmetry weight
        #pragma unroll 2
        for (int i = 0; i < 16; ++i) {               // diag region (weight 1)
            float4 dv = gp[i * 256 + t];
            value(dv.x); value(dv.y); value(dv.z); value(dv.w);
        }

        {   // hist reduction -> signature
            #pragma unroll
            for (int kk = 0; kk < KBINS; ++kk) {
                float v = acc[kk];
                #pragma unroll
                for (int off = 16; off; off >>= 1) v += __shfl_down_sync(0xffffffffu, v, off);
                if (lane == 0) hred[w * KBINS + kk] = v;
            }
            __syncthreads();
            if (t < KBINS) {
                float v = 0.f;
                #pragma unroll
                for (int ww = 0; ww < 8; ++ww) v += hred[ww * KBINS + t];
                red[t] = v;
            }
            __syncthreads();
            if (t < KBINS) {
                float tot = 0.f;
                #pragma unroll
                for (int kk = 0; kk < KBINS; ++kk) tot += red[kk];
                g_sig[b * KBINS + t] = red[t] / (tot + 1e-8f);
            }
        }
    } else {
        // ================= NT-Xent blocks (b = 256, 257): 128 rows each =================
        uint4* shZ = (uint4*)sm;
        #pragma unroll
        for (int k = 0; k < 16; ++k) {
            int idx = k * 256 + t, row = idx >> 4, u4 = idx & 15;
            const float4* Zr = (row < 128) ? ((const float4*)Z1 + row * 32)
                                           : ((const float4*)Z2 + (row - 128) * 32);
            shZ[row * ROWU4 + u4] = pack8(Zr[u4 * 2], Zr[u4 * 2 + 1]);
        }
        __syncthreads();

        {   // row-normalize (fp32 norm of quantized values, restore bf16)
            float ss = 0.f;
            #pragma unroll
            for (int u4 = 0; u4 < 16; ++u4) {
                uint4 v = shZ[t * ROWU4 + u4];
                ss += sq2f(v.x) + sq2f(v.y) + sq2f(v.z) + sq2f(v.w);
            }
            float rn = 1.f / (sqrtf(ss) + 1e-8f);
            #pragma unroll
            for (int u4 = 0; u4 < 16; ++u4) {
                uint4 v = shZ[t * ROWU4 + u4];
                unsigned int* pv = (unsigned int*)&v;
                #pragma unroll
                for (int c = 0; c < 4; ++c) {
                    float2 f = __bfloat1622float2(asbf2(pv[c]));
                    pv[c] = asu32(__floats2bfloat162_rn(f.x * rn, f.y * rn));
                }
                shZ[t * ROWU4 + u4] = v;
            }
        }
        __syncthreads();

        // thread: row gi, column half chs. Split-K bf16 Gram (fp32 chunk sums).
        const int rl  = t & 127;
        const int chs = t >> 7;
        const int gi  = (b - NGV) * 128 + rl;
        const int lab = (gi + 128) & 255;
        const float L2E = 1.4426950408889634f;
        float m = -INFINITY, ssum = 0.f, num = 0.f;
        const uint4* Arow = shZ + gi * ROWU4;

        for (int jt = 0; jt < 8; ++jt) {
            const int j0 = chs * 128 + jt * 16;
            float accf[16];
            #pragma unroll
            for (int u = 0; u < 16; ++u) accf[u] = 0.f;
            for (int cku = 0; cku < 4; ++cku) {
                __nv_bfloat162 acc2[16];
                #pragma unroll
                for (int u = 0; u < 16; ++u) acc2[u] = __floats2bfloat162_rn(0.f, 0.f);
                #pragma unroll
                for (int dd = 0; dd < 4; ++dd) {
                    const int d = cku * 4 + dd;
                    uint4 av = Arow[d];
                    __nv_bfloat162 a0 = asbf2(av.x), a1 = asbf2(av.y),
                                   a2 = asbf2(av.z), a3 = asbf2(av.w);
                    #pragma unroll
                    for (int u = 0; u < 16; ++u) {
                        uint4 bv = shZ[(j0 + u) * ROWU4 + d];
                        acc2[u] = __hfma2(a0, asbf2(bv.x), acc2[u]);
                        acc2[u] = __hfma2(a1, asbf2(bv.y), acc2[u]);
                        acc2[u] = __hfma2(a2, asbf2(bv.z), acc2[u]);
                        acc2[u] = __hfma2(a3, asbf2(bv.w), acc2[u]);
                    }
                }
                #pragma unroll
                for (int u = 0; u < 16; ++u) accf[u] += pairsum(acc2[u]);
            }
            #pragma unroll
            for (int u = 0; u < 16; ++u) {
                const int j = j0 + u;
                float v = 2.f * accf[u];
                if (j == gi)  v = -1e9f;
                if (j == lab) num = v;
                float nm = fmaxf(m, v);
                ssum = ssum * ex2f((m - nm) * L2E) + ex2f((v - nm) * L2E);
                m = nm;
            }
        }

        if (chs == 1) { red[rl] = m; red[128 + rl] = ssum; hred[rl] = num; }
        __syncthreads();
        if (chs == 0) {
            float m1 = red[rl], s1 = red[128 + rl];
            float M  = fmaxf(m, m1);
            float SS = ssum * ex2f((m - M) * L2E) + s1 * ex2f((m1 - M) * L2E);
            float nn = ((lab >> 7) == 0) ? num : hred[rl];
            sq[rl] = (M + logf(SS)) - nn;
        }
        __syncthreads();
        for (int st = 64; st > 0; st >>= 1) {
            if (t < st) sq[t] += sq[t + st];
            __syncthreads();
        }
        if (t == 0) g_ntx2[b - NGV] = sq[0];
    }
}

__global__ void k_final(float* __restrict__ out, int out_size)
{
    __shared__ float red[128];
    const int t = threadIdx.x;
    float v = 0.f;
    #pragma unroll
    for (int k = 0; k < KBINS; ++k) {
        float d = g_sig[(2 * t) * KBINS + k] - g_sig[(2 * t + 1) * KBINS + k];
        v += d * d;
    }
    red[t] = v * (1.f / (float)KBINS);
    __syncthreads();
    for (int s = 64; s > 0; s >>= 1) {
        if (t < s) red[t] += red[t + s];
        __syncthreads();
    }
    float ntx = (g_ntx2[0] + g_ntx2[1]) * (1.f / 256.f);
    float result = 0.1f * (red[0] * (1.f / 128.f) + ntx);
    for (int i = t; i < out_size; i += 128) out[i] = result;
}

extern "C" void kernel_launch(void* const* d_in, const int* in_sizes, int n_in,
                              void* d_out, int out_size)
{
    const float* H1 = (const float*)d_in[0];
    const float* H2 = (const float*)d_in[2];
    const float* Z1 = (const float*)d_in[4];
    const float* Z2 = (const float*)d_in[5];

    cudaFuncSetAttribute(k_main, cudaFuncAttributeMaxDynamicSharedMemorySize, SMEM_BYTES);

    k_main<<<NGV + 2, 256, SMEM_BYTES>>>(H1, H2, Z1, Z2);
    k_final<<<1, 128>>>((float*)d_out, out_size);
}